// round 6
// baseline (speedup 1.0000x reference)
#include <cuda_runtime.h>
#include <math.h>

#define B_   8
#define L_   2048
#define D_   512
#define Y_   8921
#define ROWS_ (B_ * Y_)          // 71368

// Scratch for deterministic loss reduction (no device allocation allowed).
__device__ float g_partials[Y_];

// Packed fp32x2 FMA (FFMA2) — 2 fp32 FMAs per issue slot; ptxas won't emit it
// from C++, PTX-only. Bit-identical rounding to scalar fmaf.
#define FMA2(d, a, b, c) \
    asm("fma.rn.f32x2 %0, %1, %2, %3;" : "=l"(d) : "l"(a), "l"(b), "l"(c))

__device__ __forceinline__ unsigned long long dup_f32x2(float v) {
    unsigned long long r;
    asm("mov.b64 %0, {%1, %1};" : "=l"(r) : "r"(__float_as_uint(v)));
    return r;
}

__device__ __forceinline__ void unpack_f32x2(unsigned long long p, float& lo, float& hi) {
    unsigned int a, b;
    asm("mov.b64 {%0, %1}, %2;" : "=r"(a), "=r"(b) : "l"(p));
    lo = __uint_as_float(a);
    hi = __uint_as_float(b);
}

// ---------------------------------------------------------------------------
// GEMM 1: scores[b,y,l] = sum_d U[y,d] * x[b,l,d]
// C tile 128(y) x 128(l), K-step 16, 256 threads, 8x8 per thread, FFMA2 core.
// ---------------------------------------------------------------------------
__global__ __launch_bounds__(256) void gemm_scores(
    const float* __restrict__ U, const float* __restrict__ X,
    float* __restrict__ S /* alpha buffer, scores out */)
{
    __shared__ float As[128][17];   // [m(y)][k] (+1 pad)
    __shared__ float Bs[16][128];   // [k][n(l)]

    const int b  = blockIdx.z;
    const int y0 = blockIdx.y * 128;
    const int l0 = blockIdx.x * 128;
    const int tid = threadIdx.x;
    const int ty = tid >> 4;
    const int tx = tid & 15;

    const float* xb = X + (size_t)b * (L_ * D_) + (size_t)l0 * D_;

    unsigned long long acc2[8][4];
#pragma unroll
    for (int i = 0; i < 8; i++)
#pragma unroll
        for (int j = 0; j < 4; j++) acc2[i][j] = 0ULL;

    for (int kb = 0; kb < D_; kb += 16) {
#pragma unroll
        for (int i = 0; i < 8; i++) {
            int f = tid + i * 256;
            int row = f >> 4;
            int col = f & 15;
            int gy = y0 + row;
            As[row][col] = (gy < Y_) ? U[(size_t)gy * D_ + kb + col] : 0.f;
        }
#pragma unroll
        for (int i = 0; i < 2; i++) {
            int f = tid + i * 256;
            int row = f >> 2;
            int c4  = (f & 3) * 4;
            float4 v = *reinterpret_cast<const float4*>(xb + (size_t)row * D_ + kb + c4);
            Bs[c4 + 0][row] = v.x;
            Bs[c4 + 1][row] = v.y;
            Bs[c4 + 2][row] = v.z;
            Bs[c4 + 3][row] = v.w;
        }
        __syncthreads();

#pragma unroll
        for (int k = 0; k < 16; k++) {
            unsigned long long a2[8];
#pragma unroll
            for (int i = 0; i < 8; i++) a2[i] = dup_f32x2(As[ty * 8 + i][k]);
            ulonglong2 q0 = *reinterpret_cast<const ulonglong2*>(&Bs[k][tx * 8]);
            ulonglong2 q1 = *reinterpret_cast<const ulonglong2*>(&Bs[k][tx * 8 + 4]);
            unsigned long long b2[4] = {q0.x, q0.y, q1.x, q1.y};
#pragma unroll
            for (int i = 0; i < 8; i++)
#pragma unroll
                for (int j = 0; j < 4; j++)
                    FMA2(acc2[i][j], a2[i], b2[j], acc2[i][j]);
        }
        __syncthreads();
    }

    // Store (alpha buffer base is only 4B-aligned -> scalar stores)
#pragma unroll
    for (int i = 0; i < 8; i++) {
        int gy = y0 + ty * 8 + i;
        if (gy < Y_) {
            float* out = S + ((size_t)b * Y_ + gy) * L_ + l0 + tx * 8;
#pragma unroll
            for (int j = 0; j < 4; j++) {
                float lo, hi;
                unpack_f32x2(acc2[i][j], lo, hi);
                out[2 * j]     = lo;
                out[2 * j + 1] = hi;
            }
        }
    }
}

// ---------------------------------------------------------------------------
// Row softmax over L=2048, in place. One block per row.
// ---------------------------------------------------------------------------
__global__ __launch_bounds__(256) void softmax_rows(float* __restrict__ S)
{
    const int r = blockIdx.x;
    float* p = S + (size_t)r * L_;
    const int t = threadIdx.x;

    float v[8];
    float mx = -3.402823466e38f;
#pragma unroll
    for (int j = 0; j < 8; j++) {
        v[j] = p[t + j * 256];
        mx = fmaxf(mx, v[j]);
    }

    __shared__ float sm[8];
#pragma unroll
    for (int o = 16; o; o >>= 1) mx = fmaxf(mx, __shfl_xor_sync(0xffffffffu, mx, o));
    if ((t & 31) == 0) sm[t >> 5] = mx;
    __syncthreads();
    mx = sm[0];
#pragma unroll
    for (int i = 1; i < 8; i++) mx = fmaxf(mx, sm[i]);
    __syncthreads();

    float sum = 0.f;
#pragma unroll
    for (int j = 0; j < 8; j++) {
        v[j] = expf(v[j] - mx);
        sum += v[j];
    }
#pragma unroll
    for (int o = 16; o; o >>= 1) sum += __shfl_xor_sync(0xffffffffu, sum, o);
    if ((t & 31) == 0) sm[t >> 5] = sum;
    __syncthreads();
    sum = 0.f;
#pragma unroll
    for (int i = 0; i < 8; i++) sum += sm[i];
    float inv = 1.f / sum;

#pragma unroll
    for (int j = 0; j < 8; j++) p[t + j * 256] = v[j] * inv;
}

// ---------------------------------------------------------------------------
// GEMM 2: m[b,y,d] = sum_l alpha[b,y,l] * x[b,l,d]  — FFMA2 core.
// ---------------------------------------------------------------------------
__global__ __launch_bounds__(256) void gemm_m(
    const float* __restrict__ A /* alpha */, const float* __restrict__ X,
    float* __restrict__ Mo)
{
    __shared__ float As[128][17];   // [m(y)][k(l)]
    __shared__ float Bs[16][128];   // [k(l)][n(d)]

    const int b  = blockIdx.z;
    const int y0 = blockIdx.y * 128;
    const int n0 = blockIdx.x * 128;
    const int tid = threadIdx.x;
    const int ty = tid >> 4;
    const int tx = tid & 15;

    const float* xb = X + (size_t)b * (L_ * D_);

    unsigned long long acc2[8][4];
#pragma unroll
    for (int i = 0; i < 8; i++)
#pragma unroll
        for (int j = 0; j < 4; j++) acc2[i][j] = 0ULL;

    for (int kb = 0; kb < L_; kb += 16) {
#pragma unroll
        for (int i = 0; i < 8; i++) {
            int f = tid + i * 256;
            int row = f >> 4;
            int col = f & 15;
            int gy = y0 + row;
            As[row][col] = (gy < Y_) ? A[((size_t)b * Y_ + gy) * L_ + kb + col] : 0.f;
        }
#pragma unroll
        for (int i = 0; i < 2; i++) {
            int f = tid + i * 256;
            int row = f >> 5;
            int c4  = (f & 31) * 4;
            *reinterpret_cast<float4*>(&Bs[row][c4]) =
                *reinterpret_cast<const float4*>(xb + (size_t)(kb + row) * D_ + n0 + c4);
        }
        __syncthreads();

#pragma unroll
        for (int k = 0; k < 16; k++) {
            unsigned long long a2[8];
#pragma unroll
            for (int i = 0; i < 8; i++) a2[i] = dup_f32x2(As[ty * 8 + i][k]);
            ulonglong2 q0 = *reinterpret_cast<const ulonglong2*>(&Bs[k][tx * 8]);
            ulonglong2 q1 = *reinterpret_cast<const ulonglong2*>(&Bs[k][tx * 8 + 4]);
            unsigned long long b2[4] = {q0.x, q0.y, q1.x, q1.y};
#pragma unroll
            for (int i = 0; i < 8; i++)
#pragma unroll
                for (int j = 0; j < 4; j++)
                    FMA2(acc2[i][j], a2[i], b2[j], acc2[i][j]);
        }
        __syncthreads();
    }

#pragma unroll
    for (int i = 0; i < 8; i++) {
        int gy = y0 + ty * 8 + i;
        if (gy < Y_) {
            float* out = Mo + ((size_t)b * Y_ + gy) * D_ + n0 + tx * 8;
#pragma unroll
            for (int j = 0; j < 4; j++) {
                float lo, hi;
                unpack_f32x2(acc2[i][j], lo, hi);
                out[2 * j]     = lo;
                out[2 * j + 1] = hi;
            }
        }
    }
}

// ---------------------------------------------------------------------------
// Head: y[g] = dot(final_weight[yy,:], m[g,:]) + bias[yy]; per-block loss partials.
// ---------------------------------------------------------------------------
__global__ __launch_bounds__(256) void head_kernel(
    const float* __restrict__ Mo, const float* __restrict__ FW,
    const float* __restrict__ bias, const float* __restrict__ target,
    float* __restrict__ Yout)
{
    const int w    = threadIdx.x >> 5;
    const int lane = threadIdx.x & 31;
    const int g    = blockIdx.x * 8 + w;
    const int yy   = g % Y_;

    const float* mr = Mo + (size_t)g * D_;
    const float* fr = FW + (size_t)yy * D_;

    float s = 0.f;
#pragma unroll
    for (int j = 0; j < 16; j++)
        s = fmaf(mr[lane + j * 32], fr[lane + j * 32], s);
#pragma unroll
    for (int o = 16; o; o >>= 1) s += __shfl_xor_sync(0xffffffffu, s, o);

    __shared__ float sm[8];
    if (lane == 0) {
        float yv = s + bias[yy];
        Yout[g] = yv;
        float t = target[g];
        sm[w] = fmaxf(yv, 0.f) - yv * t + log1pf(expf(-fabsf(yv)));
    }
    __syncthreads();
    if (threadIdx.x == 0) {
        float acc = 0.f;
#pragma unroll
        for (int i = 0; i < 8; i++) acc += sm[i];
        g_partials[blockIdx.x] = acc;
    }
}

// ---------------------------------------------------------------------------
// Final deterministic loss reduction (1 block).
// ---------------------------------------------------------------------------
__global__ __launch_bounds__(1024) void loss_reduce(float* __restrict__ out)
{
    __shared__ double sm[32];
    double s = 0.0;
    for (int i = threadIdx.x; i < Y_; i += 1024) s += (double)g_partials[i];
#pragma unroll
    for (int o = 16; o; o >>= 1) s += __shfl_xor_sync(0xffffffffu, s, o);
    if ((threadIdx.x & 31) == 0) sm[threadIdx.x >> 5] = s;
    __syncthreads();
    if (threadIdx.x == 0) {
        double acc = 0.0;
#pragma unroll
        for (int i = 0; i < 32; i++) acc += sm[i];
        out[0] = (float)(acc / (double)ROWS_);
    }
}

// ---------------------------------------------------------------------------
// Launch. Inputs: x, target, text_inputs(unused), U_weight, final_weight,
// final_bias. Output tuple: (y, loss, alpha, m) flattened.
// ---------------------------------------------------------------------------
extern "C" void kernel_launch(void* const* d_in, const int* in_sizes, int n_in,
                              void* d_out, int out_size)
{
    const float* x      = (const float*)d_in[0];
    const float* target = (const float*)d_in[1];
    const float* U      = (const float*)d_in[3];
    const float* FW     = (const float*)d_in[4];
    const float* bias   = (const float*)d_in[5];

    float* out       = (float*)d_out;
    float* out_y     = out;
    float* out_loss  = out + (size_t)ROWS_;
    float* out_alpha = out + (size_t)ROWS_ + 1;
    float* out_m     = out_alpha + (size_t)B_ * Y_ * L_;

    dim3 g1(L_ / 128, (Y_ + 127) / 128, B_);
    gemm_scores<<<g1, 256>>>(U, x, out_alpha);

    softmax_rows<<<ROWS_, 256>>>(out_alpha);

    dim3 g2(D_ / 128, (Y_ + 127) / 128, B_);
    gemm_m<<<g2, 256>>>(out_alpha, x, out_m);

    head_kernel<<<Y_, 256>>>(out_m, FW, bias, target, out_y);
    loss_reduce<<<1, 1024>>>(out_loss);
}

// round 11
// speedup vs baseline: 2.5412x; 2.5412x over previous
#include <cuda_runtime.h>
#include <cuda_bf16.h>
#include <math.h>
#include <stdint.h>

#define B_    8
#define L_    2048
#define D_    512
#define Y_    8921
#define YPAD_ 8960                 // 70 * 128
#define ROWS_ (B_ * Y_)            // 71368

// ---- static device scratch (no runtime allocation allowed) ----
__device__ float g_partials[Y_];
__device__ __align__(16) __nv_bfloat16 g_U_hi[YPAD_ * D_];
__device__ __align__(16) __nv_bfloat16 g_U_lo[YPAD_ * D_];
__device__ __align__(16) __nv_bfloat16 g_x_hi[B_ * L_ * D_];                  // [b][l][d]
__device__ __align__(16) __nv_bfloat16 g_x_lo[B_ * L_ * D_];
__device__ __align__(16) __nv_bfloat16 g_xT_hi[B_ * D_ * L_];                 // [b][d][l]
__device__ __align__(16) __nv_bfloat16 g_xT_lo[B_ * D_ * L_];
__device__ __align__(16) __nv_bfloat16 g_alpha_hi[(size_t)B_ * YPAD_ * L_];
__device__ __align__(16) __nv_bfloat16 g_alpha_lo[(size_t)B_ * YPAD_ * L_];

// ---- helpers ----
__device__ __forceinline__ uint32_t smem_u32(const void* p) {
    uint32_t a;
    asm("{ .reg .u64 t; cvta.to.shared.u64 t, %1; cvt.u32.u64 %0, t; }" : "=r"(a) : "l"(p));
    return a;
}
__device__ __forceinline__ uint32_t lds32(uint32_t addr) {
    uint32_t v;
    asm volatile("ld.shared.b32 %0, [%1];" : "=r"(v) : "r"(addr));
    return v;
}
__device__ __forceinline__ void mma16816(float* c, const uint32_t* a, const uint32_t* b) {
    asm volatile("mma.sync.aligned.m16n8k16.row.col.f32.bf16.bf16.f32 "
        "{%0,%1,%2,%3}, {%4,%5,%6,%7}, {%8,%9}, {%0,%1,%2,%3};"
        : "+f"(c[0]), "+f"(c[1]), "+f"(c[2]), "+f"(c[3])
        : "r"(a[0]), "r"(a[1]), "r"(a[2]), "r"(a[3]), "r"(b[0]), "r"(b[1]));
}

// SMEM tile geometry: 128 rows x 32 bf16 (64B data) with 80B pitch.
// 80B = 20 words -> fragment-load banks (20*grp + tig) mod 32: conflict-free.
#define PITCH_B   80
#define TILE_SB   (128 * PITCH_B)     // 10240
// 4 tiles (A_hi, A_lo, B_hi, B_lo) = 40960 bytes of STATIC shared memory.

// Plain ld.global.v4 + st.shared.v4 of one 128(rows) x 32(k bf16 = 64B) tile.
__device__ __forceinline__ void ld_tile32(uint32_t dst, const __nv_bfloat16* __restrict__ src,
                                          int kb, int ldk, int tid)
{
#pragma unroll
    for (int i = 0; i < 2; i++) {
        int seg = tid + i * 256;            // 0..511 segments of 16B
        int row = seg >> 2;                 // 4 segments per row
        int u   = seg & 3;
        uint4 v = *reinterpret_cast<const uint4*>(src + (size_t)row * ldk + kb + u * 8);
        uint32_t d = dst + (uint32_t)row * PITCH_B + (uint32_t)(u << 4);
        asm volatile("st.shared.v4.b32 [%0], {%1,%2,%3,%4};"
                     :: "r"(d), "r"(v.x), "r"(v.y), "r"(v.z), "r"(v.w));
    }
}

// ---------------------------------------------------------------------------
// HMMA GEMM body: C[m][n] = sum_k A[m][k] * B[n][k] for this CTA's 128x128 tile.
// A,B pre-split bf16 hi/lo, K-contiguous. fp32 accumulate, 3-product split.
// 8 warps (4m x 2n), K-chunk 32, single-buffered static smem.
// Fragments per the PTX mma.m16n8k16 thread mapping (direct lds, no swizzle).
// Pointers are DEVICE-side (global symbols bound in the __global__ wrappers).
// ---------------------------------------------------------------------------
__device__ __forceinline__ void gemm_body(
    const __nv_bfloat16* pAh, const __nv_bfloat16* pAl,
    const __nv_bfloat16* pBh, const __nv_bfloat16* pBl,
    int ldkA, int ldkB, int K,
    float* outp, int ldo, int y0, int n0)
{
    __shared__ __align__(16) uint8_t smem[4 * TILE_SB];   // 40 KB static
    uint32_t sb = smem_u32(smem);
    const uint32_t sAh = sb;
    const uint32_t sAl = sb + TILE_SB;
    const uint32_t sBh = sb + 2 * TILE_SB;
    const uint32_t sBl = sb + 3 * TILE_SB;

    const int tid  = threadIdx.x;
    const int lane = tid & 31;
    const int wid  = tid >> 5;
    const int grp  = lane >> 2;            // groupID (0..7)
    const int tig  = lane & 3;             // threadID_in_group (0..3)
    const int wm = wid & 3;                // 4 m-groups of 32 rows
    const int wn = wid >> 2;               // 2 n-groups of 64 cols

    float acc[2][8][4];
#pragma unroll
    for (int t = 0; t < 2; t++)
#pragma unroll
        for (int q = 0; q < 8; q++)
#pragma unroll
            for (int e = 0; e < 4; e++) acc[t][q][e] = 0.f;

    const int NC = K >> 5;                 // K-chunk 32
    for (int c = 0; c < NC; c++) {
        __syncthreads();                    // previous chunk's reads complete
        int kb = c * 32;
        ld_tile32(sAh, pAh, kb, ldkA, tid);
        ld_tile32(sAl, pAl, kb, ldkA, tid);
        ld_tile32(sBh, pBh, kb, ldkB, tid);
        ld_tile32(sBl, pBl, kb, ldkB, tid);
        __syncthreads();

#pragma unroll
        for (int s = 0; s < 2; s++) {       // two k16 steps in the 32-chunk
            // --- A fragments (hi & lo); t = 0,1 -> rows wm*32 + t*16 + ... ---
            uint32_t ahf[2][4], alf[2][4];
#pragma unroll
            for (int t = 0; t < 2; t++) {
                int r = wm * 32 + t * 16 + grp;
                uint32_t o0 = (uint32_t)r * PITCH_B + (uint32_t)((s * 16 + tig * 2) * 2);
                ahf[t][0] = lds32(sAh + o0);                       // (r,   k)
                ahf[t][1] = lds32(sAh + o0 + 8 * PITCH_B);         // (r+8, k)
                ahf[t][2] = lds32(sAh + o0 + 16);                  // (r,   k+8)
                ahf[t][3] = lds32(sAh + o0 + 8 * PITCH_B + 16);    // (r+8, k+8)
                alf[t][0] = lds32(sAl + o0);
                alf[t][1] = lds32(sAl + o0 + 8 * PITCH_B);
                alf[t][2] = lds32(sAl + o0 + 16);
                alf[t][3] = lds32(sAl + o0 + 8 * PITCH_B + 16);
            }
            // --- B fragments per n8 block j, then 3 split MMAs ---
#pragma unroll
            for (int j = 0; j < 8; j++) {
                int n = wn * 64 + j * 8 + grp;
                uint32_t ob = (uint32_t)n * PITCH_B + (uint32_t)((s * 16 + tig * 2) * 2);
                uint32_t bhf[2], blf[2];
                bhf[0] = lds32(sBh + ob);           // (n, k..k+1)
                bhf[1] = lds32(sBh + ob + 16);      // (n, k+8..k+9)
                blf[0] = lds32(sBl + ob);
                blf[1] = lds32(sBl + ob + 16);
#pragma unroll
                for (int t = 0; t < 2; t++) {
                    mma16816(acc[t][j], ahf[t], bhf);
                    mma16816(acc[t][j], ahf[t], blf);
                    mma16816(acc[t][j], alf[t], bhf);
                }
            }
        }
    }

    // Epilogue: direct stores. Quad (tig 0..3) covers 8 consecutive cols of one
    // row -> each 32B sector fully written. Guard m-rows >= Y_ (padding).
#pragma unroll
    for (int t = 0; t < 2; t++) {
        int r  = y0 + wm * 32 + t * 16 + grp;
#pragma unroll
        for (int q = 0; q < 8; q++) {
            int cc = n0 + wn * 64 + q * 8 + tig * 2;
            if (r < Y_) {
                outp[(size_t)r * ldo + cc]     = acc[t][q][0];
                outp[(size_t)r * ldo + cc + 1] = acc[t][q][1];
            }
            if (r + 8 < Y_) {
                outp[(size_t)(r + 8) * ldo + cc]     = acc[t][q][2];
                outp[(size_t)(r + 8) * ldo + cc + 1] = acc[t][q][3];
            }
        }
    }
}

// GEMM1 wrapper: scores[b,y,l] = U[y,:] . x[b,l,:]
// Device-global operands bound HERE (device code), not passed from host.
__global__ void __launch_bounds__(256) gemm1_k(float* __restrict__ Sout)
{
    const int b  = blockIdx.z;
    const int y0 = blockIdx.y * 128;
    const int l0 = blockIdx.x * 128;
    gemm_body(g_U_hi + (size_t)y0 * D_,
              g_U_lo + (size_t)y0 * D_,
              g_x_hi + ((size_t)b * L_ + l0) * D_,
              g_x_lo + ((size_t)b * L_ + l0) * D_,
              D_, D_, D_,
              Sout + (size_t)b * Y_ * L_, L_, y0, l0);
}

// GEMM2 wrapper: m[b,y,d] = alpha[b,y,:] . xT[b,d,:]
__global__ void __launch_bounds__(256) gemm2_k(float* __restrict__ Mout)
{
    const int b  = blockIdx.z;
    const int y0 = blockIdx.y * 128;
    const int n0 = blockIdx.x * 128;
    gemm_body(g_alpha_hi + ((size_t)b * YPAD_ + y0) * L_,
              g_alpha_lo + ((size_t)b * YPAD_ + y0) * L_,
              g_xT_hi + ((size_t)b * D_ + n0) * L_,
              g_xT_lo + ((size_t)b * D_ + n0) * L_,
              L_, L_, L_,
              Mout + (size_t)b * Y_ * D_, D_, y0, n0);
}

// ---------------------------------------------------------------------------
// Prep: split U (zero-padded to YPAD rows) and x (plus transposed xT).
// ---------------------------------------------------------------------------
__global__ __launch_bounds__(256) void split_U_kernel(const float* __restrict__ U)
{
    int idx = blockIdx.x * 256 + threadIdx.x;     // over YPAD_*D_
    int y = idx >> 9;
    float v = (y < Y_) ? U[idx] : 0.f;
    __nv_bfloat16 h = __float2bfloat16(v);
    g_U_hi[idx] = h;
    g_U_lo[idx] = __float2bfloat16(v - __bfloat162float(h));
}

__global__ __launch_bounds__(256) void split_x_kernel(const float* __restrict__ X)
{
    __shared__ float tile[32][33];
    int b = blockIdx.z, d0 = blockIdx.x * 32, l0 = blockIdx.y * 32;
    int tx = threadIdx.x, ty = threadIdx.y;       // (32, 8)
#pragma unroll
    for (int i = 0; i < 4; i++) {
        int l = l0 + ty + i * 8;
        size_t o = ((size_t)b * L_ + l) * D_ + d0 + tx;
        float v = X[o];
        tile[ty + i * 8][tx] = v;
        __nv_bfloat16 h = __float2bfloat16(v);
        g_x_hi[o] = h;
        g_x_lo[o] = __float2bfloat16(v - __bfloat162float(h));
    }
    __syncthreads();
#pragma unroll
    for (int i = 0; i < 4; i++) {
        int d = d0 + ty + i * 8;
        float v = tile[tx][ty + i * 8];
        size_t o = ((size_t)b * D_ + d) * L_ + l0 + tx;
        __nv_bfloat16 h = __float2bfloat16(v);
        g_xT_hi[o] = h;
        g_xT_lo[o] = __float2bfloat16(v - __bfloat162float(h));
    }
}

// ---------------------------------------------------------------------------
// Softmax over L=2048 rows, in place; also emits bf16 hi/lo split of alpha.
// ---------------------------------------------------------------------------
__global__ __launch_bounds__(256) void softmax_split(float* __restrict__ S)
{
    const int r = blockIdx.x;                     // 0..ROWS_-1
    const int b = r / Y_, y = r - b * Y_;
    float* p = S + (size_t)r * L_;
    __nv_bfloat16* ph = g_alpha_hi + ((size_t)b * YPAD_ + y) * L_;
    __nv_bfloat16* pl = g_alpha_lo + ((size_t)b * YPAD_ + y) * L_;
    const int t = threadIdx.x;

    float v[8];
    float mx = -3.402823466e38f;
#pragma unroll
    for (int j = 0; j < 8; j++) {
        v[j] = p[t + j * 256];
        mx = fmaxf(mx, v[j]);
    }
    __shared__ float sm[8];
#pragma unroll
    for (int o = 16; o; o >>= 1) mx = fmaxf(mx, __shfl_xor_sync(0xffffffffu, mx, o));
    if ((t & 31) == 0) sm[t >> 5] = mx;
    __syncthreads();
    mx = sm[0];
#pragma unroll
    for (int i = 1; i < 8; i++) mx = fmaxf(mx, sm[i]);
    __syncthreads();

    float sum = 0.f;
#pragma unroll
    for (int j = 0; j < 8; j++) { v[j] = expf(v[j] - mx); sum += v[j]; }
#pragma unroll
    for (int o = 16; o; o >>= 1) sum += __shfl_xor_sync(0xffffffffu, sum, o);
    if ((t & 31) == 0) sm[t >> 5] = sum;
    __syncthreads();
    sum = 0.f;
#pragma unroll
    for (int i = 0; i < 8; i++) sum += sm[i];
    float inv = 1.f / sum;

#pragma unroll
    for (int j = 0; j < 8; j++) {
        float o = v[j] * inv;
        int ix = t + j * 256;
        p[ix] = o;
        __nv_bfloat16 h = __float2bfloat16(o);
        ph[ix] = h;
        pl[ix] = __float2bfloat16(o - __bfloat162float(h));
    }
}

// ---------------------------------------------------------------------------
// Head + loss (unchanged from the passing R5 kernel).
// ---------------------------------------------------------------------------
__global__ __launch_bounds__(256) void head_kernel(
    const float* __restrict__ Mo, const float* __restrict__ FW,
    const float* __restrict__ bias, const float* __restrict__ target,
    float* __restrict__ Yout)
{
    const int w = threadIdx.x >> 5, lane = threadIdx.x & 31;
    const int g = blockIdx.x * 8 + w;
    const int yy = g % Y_;
    const float* mr = Mo + (size_t)g * D_;
    const float* fr = FW + (size_t)yy * D_;

    float s = 0.f;
#pragma unroll
    for (int j = 0; j < 16; j++)
        s = fmaf(mr[lane + j * 32], fr[lane + j * 32], s);
#pragma unroll
    for (int o = 16; o; o >>= 1) s += __shfl_xor_sync(0xffffffffu, s, o);

    __shared__ float sm[8];
    if (lane == 0) {
        float yv = s + bias[yy];
        Yout[g] = yv;
        float t = target[g];
        sm[w] = fmaxf(yv, 0.f) - yv * t + log1pf(expf(-fabsf(yv)));
    }
    __syncthreads();
    if (threadIdx.x == 0) {
        float acc = 0.f;
#pragma unroll
        for (int i = 0; i < 8; i++) acc += sm[i];
        g_partials[blockIdx.x] = acc;
    }
}

__global__ __launch_bounds__(1024) void loss_reduce(float* __restrict__ out)
{
    __shared__ double sm[32];
    double s = 0.0;
    for (int i = threadIdx.x; i < Y_; i += 1024) s += (double)g_partials[i];
#pragma unroll
    for (int o = 16; o; o >>= 1) s += __shfl_xor_sync(0xffffffffu, s, o);
    if ((threadIdx.x & 31) == 0) sm[threadIdx.x >> 5] = s;
    __syncthreads();
    if (threadIdx.x == 0) {
        double acc = 0.0;
#pragma unroll
        for (int i = 0; i < 32; i++) acc += sm[i];
        out[0] = (float)(acc / (double)ROWS_);
    }
}

// ---------------------------------------------------------------------------
// Launch. Inputs: x, target, text_inputs(unused), U_weight, final_weight,
// final_bias. Output tuple: (y, loss, alpha, m) flattened into d_out.
// NOTE: only harness-provided device pointers cross the host/device boundary;
// all __device__ scratch arrays are referenced from device code only.
// ---------------------------------------------------------------------------
extern "C" void kernel_launch(void* const* d_in, const int* in_sizes, int n_in,
                              void* d_out, int out_size)
{
    const float* x      = (const float*)d_in[0];
    const float* target = (const float*)d_in[1];
    const float* U      = (const float*)d_in[3];
    const float* FW     = (const float*)d_in[4];
    const float* bias   = (const float*)d_in[5];

    float* out       = (float*)d_out;
    float* out_y     = out;
    float* out_loss  = out + (size_t)ROWS_;
    float* out_alpha = out + (size_t)ROWS_ + 1;
    float* out_m     = out_alpha + (size_t)B_ * Y_ * L_;

    split_U_kernel<<<YPAD_ * D_ / 256, 256>>>(U);
    split_x_kernel<<<dim3(D_ / 32, L_ / 32, B_), dim3(32, 8)>>>(x);

    gemm1_k<<<dim3(L_ / 128, YPAD_ / 128, B_), 256>>>(out_alpha);

    softmax_split<<<ROWS_, 256>>>(out_alpha);

    gemm2_k<<<dim3(D_ / 128, YPAD_ / 128, B_), 256>>>(out_m);

    head_kernel<<<Y_, 256>>>(out_m, FW, bias, target, out_y);
    loss_reduce<<<1, 1024>>>(out_loss);
}

// round 12
// speedup vs baseline: 3.0796x; 1.2119x over previous
#include <cuda_runtime.h>
#include <cuda_bf16.h>
#include <math.h>
#include <stdint.h>

#define B_    8
#define L_    2048
#define D_    512
#define Y_    8921
#define YPAD_ 8960                 // 70 * 128
#define ROWS_ (B_ * Y_)            // 71368

// ---- static device scratch (no runtime allocation allowed) ----
__device__ float g_partials[Y_];
__device__ __align__(16) __nv_bfloat16 g_U_hi[YPAD_ * D_];
__device__ __align__(16) __nv_bfloat16 g_U_lo[YPAD_ * D_];
__device__ __align__(16) __nv_bfloat16 g_x_hi[B_ * L_ * D_];                  // [b][l][d]
__device__ __align__(16) __nv_bfloat16 g_x_lo[B_ * L_ * D_];
__device__ __align__(16) __nv_bfloat16 g_xT_hi[B_ * D_ * L_];                 // [b][d][l]
__device__ __align__(16) __nv_bfloat16 g_xT_lo[B_ * D_ * L_];
__device__ __align__(16) __nv_bfloat16 g_alpha_hi[(size_t)B_ * YPAD_ * L_];
__device__ __align__(16) __nv_bfloat16 g_alpha_lo[(size_t)B_ * YPAD_ * L_];

// ---- helpers ----
__device__ __forceinline__ uint32_t smem_u32(const void* p) {
    uint32_t a;
    asm("{ .reg .u64 t; cvta.to.shared.u64 t, %1; cvt.u32.u64 %0, t; }" : "=r"(a) : "l"(p));
    return a;
}
__device__ __forceinline__ uint32_t lds32(uint32_t addr) {
    uint32_t v;
    asm volatile("ld.shared.b32 %0, [%1];" : "=r"(v) : "r"(addr));
    return v;
}
__device__ __forceinline__ void mma16816(float* c, const uint32_t* a, const uint32_t* b) {
    asm volatile("mma.sync.aligned.m16n8k16.row.col.f32.bf16.bf16.f32 "
        "{%0,%1,%2,%3}, {%4,%5,%6,%7}, {%8,%9}, {%0,%1,%2,%3};"
        : "+f"(c[0]), "+f"(c[1]), "+f"(c[2]), "+f"(c[3])
        : "r"(a[0]), "r"(a[1]), "r"(a[2]), "r"(a[3]), "r"(b[0]), "r"(b[1]));
}

// SMEM tile geometry: 128 rows x 32 bf16 (64B data) with 80B pitch.
// 80B = 20 words -> fragment-load banks (20*grp + tig) mod 32: conflict-free.
#define PITCH_B   80
#define TILE_SB   (128 * PITCH_B)     // 10240
#define STAGE_SB  (4 * TILE_SB)       // 40960 (A_hi, A_lo, B_hi, B_lo)
#define SMEM_GEMM (2 * STAGE_SB)      // 81920, double-buffered

// cp.async one 128(rows) x 32(k bf16 = 64B) tile into padded-pitch SMEM.
// Same addressing as the verified synchronous loader.
__device__ __forceinline__ void cp_tile32(uint32_t dst, const __nv_bfloat16* __restrict__ src,
                                          int kb, int ldk, int tid)
{
#pragma unroll
    for (int i = 0; i < 2; i++) {
        int seg = tid + i * 256;            // 0..511 segments of 16B
        int row = seg >> 2;                 // 4 segments per row
        int u   = seg & 3;
        const void* g = src + (size_t)row * ldk + kb + u * 8;
        uint32_t d = dst + (uint32_t)row * PITCH_B + (uint32_t)(u << 4);
        asm volatile("cp.async.ca.shared.global [%0], [%1], 16;" :: "r"(d), "l"(g));
    }
}

// ---------------------------------------------------------------------------
// HMMA GEMM body: C[m][n] = sum_k A[m][k] * B[n][k] for this CTA's 128x128 tile.
// A,B pre-split bf16 hi/lo, K-contiguous. fp32 accumulate, 3-product split.
// 8 warps (4m x 2n), K-chunk 32, cp.async 2-stage pipeline (dynamic smem).
// Fragment math identical to the verified R11 kernel.
// ---------------------------------------------------------------------------
__device__ __forceinline__ void gemm_body(
    const __nv_bfloat16* pAh, const __nv_bfloat16* pAl,
    const __nv_bfloat16* pBh, const __nv_bfloat16* pBl,
    int ldkA, int ldkB, int K,
    float* outp, int ldo, int y0, int n0)
{
    extern __shared__ __align__(16) uint8_t smem[];
    uint32_t sb = smem_u32(smem);

    const int tid  = threadIdx.x;
    const int lane = tid & 31;
    const int wid  = tid >> 5;
    const int grp  = lane >> 2;            // groupID (0..7)
    const int tig  = lane & 3;             // threadID_in_group (0..3)
    const int wm = wid & 3;                // 4 m-groups of 32 rows
    const int wn = wid >> 2;               // 2 n-groups of 64 cols

    float acc[2][8][4];
#pragma unroll
    for (int t = 0; t < 2; t++)
#pragma unroll
        for (int q = 0; q < 8; q++)
#pragma unroll
            for (int e = 0; e < 4; e++) acc[t][q][e] = 0.f;

    const int NC = K >> 5;                 // K-chunk 32

    // prologue: chunk 0 -> stage 0
    {
        uint32_t st = sb;
        cp_tile32(st,               pAh, 0, ldkA, tid);
        cp_tile32(st + TILE_SB,     pAl, 0, ldkA, tid);
        cp_tile32(st + 2 * TILE_SB, pBh, 0, ldkB, tid);
        cp_tile32(st + 3 * TILE_SB, pBl, 0, ldkB, tid);
        asm volatile("cp.async.commit_group;");
    }

    for (int c = 0; c < NC; c++) {
        // issue loads for chunk c+1 into the other stage (holds chunk c-1,
        // whose compute finished before the end-of-iteration barrier).
        if (c + 1 < NC) {
            uint32_t st = sb + (uint32_t)((c + 1) & 1) * STAGE_SB;
            int kb = (c + 1) * 32;
            cp_tile32(st,               pAh, kb, ldkA, tid);
            cp_tile32(st + TILE_SB,     pAl, kb, ldkA, tid);
            cp_tile32(st + 2 * TILE_SB, pBh, kb, ldkB, tid);
            cp_tile32(st + 3 * TILE_SB, pBl, kb, ldkB, tid);
            asm volatile("cp.async.commit_group;");
            asm volatile("cp.async.wait_group 1;");   // chunk c complete
        } else {
            asm volatile("cp.async.wait_group 0;");
        }
        __syncthreads();                               // chunk c visible to all

        uint32_t st  = sb + (uint32_t)(c & 1) * STAGE_SB;
        const uint32_t sAh = st;
        const uint32_t sAl = st + TILE_SB;
        const uint32_t sBh = st + 2 * TILE_SB;
        const uint32_t sBl = st + 3 * TILE_SB;

#pragma unroll
        for (int s = 0; s < 2; s++) {       // two k16 steps in the 32-chunk
            // --- A fragments (hi & lo); t = 0,1 -> rows wm*32 + t*16 + ... ---
            uint32_t ahf[2][4], alf[2][4];
#pragma unroll
            for (int t = 0; t < 2; t++) {
                int r = wm * 32 + t * 16 + grp;
                uint32_t o0 = (uint32_t)r * PITCH_B + (uint32_t)((s * 16 + tig * 2) * 2);
                ahf[t][0] = lds32(sAh + o0);                       // (r,   k)
                ahf[t][1] = lds32(sAh + o0 + 8 * PITCH_B);         // (r+8, k)
                ahf[t][2] = lds32(sAh + o0 + 16);                  // (r,   k+8)
                ahf[t][3] = lds32(sAh + o0 + 8 * PITCH_B + 16);    // (r+8, k+8)
                alf[t][0] = lds32(sAl + o0);
                alf[t][1] = lds32(sAl + o0 + 8 * PITCH_B);
                alf[t][2] = lds32(sAl + o0 + 16);
                alf[t][3] = lds32(sAl + o0 + 8 * PITCH_B + 16);
            }
            // --- B fragments per n8 block j, then 3 split MMAs ---
#pragma unroll
            for (int j = 0; j < 8; j++) {
                int n = wn * 64 + j * 8 + grp;
                uint32_t ob = (uint32_t)n * PITCH_B + (uint32_t)((s * 16 + tig * 2) * 2);
                uint32_t bhf[2], blf[2];
                bhf[0] = lds32(sBh + ob);           // (n, k..k+1)
                bhf[1] = lds32(sBh + ob + 16);      // (n, k+8..k+9)
                blf[0] = lds32(sBl + ob);
                blf[1] = lds32(sBl + ob + 16);
#pragma unroll
                for (int t = 0; t < 2; t++) {
                    mma16816(acc[t][j], ahf[t], bhf);
                    mma16816(acc[t][j], ahf[t], blf);
                    mma16816(acc[t][j], alf[t], bhf);
                }
            }
        }
        __syncthreads();    // all warps done reading stage (c&1) before reuse
    }

    // Epilogue: direct stores. Quad (tig 0..3) covers 8 consecutive cols of one
    // row -> each 32B sector fully written. Guard m-rows >= Y_ (padding).
#pragma unroll
    for (int t = 0; t < 2; t++) {
        int r  = y0 + wm * 32 + t * 16 + grp;
#pragma unroll
        for (int q = 0; q < 8; q++) {
            int cc = n0 + wn * 64 + q * 8 + tig * 2;
            if (r < Y_) {
                outp[(size_t)r * ldo + cc]     = acc[t][q][0];
                outp[(size_t)r * ldo + cc + 1] = acc[t][q][1];
            }
            if (r + 8 < Y_) {
                outp[(size_t)(r + 8) * ldo + cc]     = acc[t][q][2];
                outp[(size_t)(r + 8) * ldo + cc + 1] = acc[t][q][3];
            }
        }
    }
}

// GEMM1 wrapper: scores[b,y,l] = U[y,:] . x[b,l,:]
// Device-global operands bound HERE (device code), not passed from host.
__global__ void __launch_bounds__(256) gemm1_k(float* __restrict__ Sout)
{
    const int b  = blockIdx.z;
    const int y0 = blockIdx.y * 128;
    const int l0 = blockIdx.x * 128;
    gemm_body(g_U_hi + (size_t)y0 * D_,
              g_U_lo + (size_t)y0 * D_,
              g_x_hi + ((size_t)b * L_ + l0) * D_,
              g_x_lo + ((size_t)b * L_ + l0) * D_,
              D_, D_, D_,
              Sout + (size_t)b * Y_ * L_, L_, y0, l0);
}

// GEMM2 wrapper: m[b,y,d] = alpha[b,y,:] . xT[b,d,:]
__global__ void __launch_bounds__(256) gemm2_k(float* __restrict__ Mout)
{
    const int b  = blockIdx.z;
    const int y0 = blockIdx.y * 128;
    const int n0 = blockIdx.x * 128;
    gemm_body(g_alpha_hi + ((size_t)b * YPAD_ + y0) * L_,
              g_alpha_lo + ((size_t)b * YPAD_ + y0) * L_,
              g_xT_hi + ((size_t)b * D_ + n0) * L_,
              g_xT_lo + ((size_t)b * D_ + n0) * L_,
              L_, L_, L_,
              Mout + (size_t)b * Y_ * D_, D_, y0, n0);
}

// ---------------------------------------------------------------------------
// Prep: split U (zero-padded to YPAD rows) and x (plus transposed xT).
// ---------------------------------------------------------------------------
__global__ __launch_bounds__(256) void split_U_kernel(const float* __restrict__ U)
{
    int idx = blockIdx.x * 256 + threadIdx.x;     // over YPAD_*D_
    int y = idx >> 9;
    float v = (y < Y_) ? U[idx] : 0.f;
    __nv_bfloat16 h = __float2bfloat16(v);
    g_U_hi[idx] = h;
    g_U_lo[idx] = __float2bfloat16(v - __bfloat162float(h));
}

__global__ __launch_bounds__(256) void split_x_kernel(const float* __restrict__ X)
{
    __shared__ float tile[32][33];
    int b = blockIdx.z, d0 = blockIdx.x * 32, l0 = blockIdx.y * 32;
    int tx = threadIdx.x, ty = threadIdx.y;       // (32, 8)
#pragma unroll
    for (int i = 0; i < 4; i++) {
        int l = l0 + ty + i * 8;
        size_t o = ((size_t)b * L_ + l) * D_ + d0 + tx;
        float v = X[o];
        tile[ty + i * 8][tx] = v;
        __nv_bfloat16 h = __float2bfloat16(v);
        g_x_hi[o] = h;
        g_x_lo[o] = __float2bfloat16(v - __bfloat162float(h));
    }
    __syncthreads();
#pragma unroll
    for (int i = 0; i < 4; i++) {
        int d = d0 + ty + i * 8;
        float v = tile[tx][ty + i * 8];
        size_t o = ((size_t)b * D_ + d) * L_ + l0 + tx;
        __nv_bfloat16 h = __float2bfloat16(v);
        g_xT_hi[o] = h;
        g_xT_lo[o] = __float2bfloat16(v - __bfloat162float(h));
    }
}

// ---------------------------------------------------------------------------
// Softmax over L=2048 rows, in place; also emits bf16 hi/lo split of alpha.
// ---------------------------------------------------------------------------
__global__ __launch_bounds__(256) void softmax_split(float* __restrict__ S)
{
    const int r = blockIdx.x;                     // 0..ROWS_-1
    const int b = r / Y_, y = r - b * Y_;
    float* p = S + (size_t)r * L_;
    __nv_bfloat16* ph = g_alpha_hi + ((size_t)b * YPAD_ + y) * L_;
    __nv_bfloat16* pl = g_alpha_lo + ((size_t)b * YPAD_ + y) * L_;
    const int t = threadIdx.x;

    float v[8];
    float mx = -3.402823466e38f;
#pragma unroll
    for (int j = 0; j < 8; j++) {
        v[j] = p[t + j * 256];
        mx = fmaxf(mx, v[j]);
    }
    __shared__ float sm[8];
#pragma unroll
    for (int o = 16; o; o >>= 1) mx = fmaxf(mx, __shfl_xor_sync(0xffffffffu, mx, o));
    if ((t & 31) == 0) sm[t >> 5] = mx;
    __syncthreads();
    mx = sm[0];
#pragma unroll
    for (int i = 1; i < 8; i++) mx = fmaxf(mx, sm[i]);
    __syncthreads();

    float sum = 0.f;
#pragma unroll
    for (int j = 0; j < 8; j++) { v[j] = expf(v[j] - mx); sum += v[j]; }
#pragma unroll
    for (int o = 16; o; o >>= 1) sum += __shfl_xor_sync(0xffffffffu, sum, o);
    if ((t & 31) == 0) sm[t >> 5] = sum;
    __syncthreads();
    sum = 0.f;
#pragma unroll
    for (int i = 0; i < 8; i++) sum += sm[i];
    float inv = 1.f / sum;

#pragma unroll
    for (int j = 0; j < 8; j++) {
        float o = v[j] * inv;
        int ix = t + j * 256;
        p[ix] = o;
        __nv_bfloat16 h = __float2bfloat16(o);
        ph[ix] = h;
        pl[ix] = __float2bfloat16(o - __bfloat162float(h));
    }
}

// ---------------------------------------------------------------------------
// Head + loss (unchanged).
// ---------------------------------------------------------------------------
__global__ __launch_bounds__(256) void head_kernel(
    const float* __restrict__ Mo, const float* __restrict__ FW,
    const float* __restrict__ bias, const float* __restrict__ target,
    float* __restrict__ Yout)
{
    const int w = threadIdx.x >> 5, lane = threadIdx.x & 31;
    const int g = blockIdx.x * 8 + w;
    const int yy = g % Y_;
    const float* mr = Mo + (size_t)g * D_;
    const float* fr = FW + (size_t)yy * D_;

    float s = 0.f;
#pragma unroll
    for (int j = 0; j < 16; j++)
        s = fmaf(mr[lane + j * 32], fr[lane + j * 32], s);
#pragma unroll
    for (int o = 16; o; o >>= 1) s += __shfl_xor_sync(0xffffffffu, s, o);

    __shared__ float sm[8];
    if (lane == 0) {
        float yv = s + bias[yy];
        Yout[g] = yv;
        float t = target[g];
        sm[w] = fmaxf(yv, 0.f) - yv * t + log1pf(expf(-fabsf(yv)));
    }
    __syncthreads();
    if (threadIdx.x == 0) {
        float acc = 0.f;
#pragma unroll
        for (int i = 0; i < 8; i++) acc += sm[i];
        g_partials[blockIdx.x] = acc;
    }
}

__global__ __launch_bounds__(1024) void loss_reduce(float* __restrict__ out)
{
    __shared__ double sm[32];
    double s = 0.0;
    for (int i = threadIdx.x; i < Y_; i += 1024) s += (double)g_partials[i];
#pragma unroll
    for (int o = 16; o; o >>= 1) s += __shfl_xor_sync(0xffffffffu, s, o);
    if ((threadIdx.x & 31) == 0) sm[threadIdx.x >> 5] = s;
    __syncthreads();
    if (threadIdx.x == 0) {
        double acc = 0.0;
#pragma unroll
        for (int i = 0; i < 32; i++) acc += sm[i];
        out[0] = (float)(acc / (double)ROWS_);
    }
}

// ---------------------------------------------------------------------------
// Launch. Inputs: x, target, text_inputs(unused), U_weight, final_weight,
// final_bias. Output tuple: (y, loss, alpha, m) flattened into d_out.
// Only harness-provided device pointers cross the host/device boundary.
// ---------------------------------------------------------------------------
extern "C" void kernel_launch(void* const* d_in, const int* in_sizes, int n_in,
                              void* d_out, int out_size)
{
    const float* x      = (const float*)d_in[0];
    const float* target = (const float*)d_in[1];
    const float* U      = (const float*)d_in[3];
    const float* FW     = (const float*)d_in[4];
    const float* bias   = (const float*)d_in[5];

    float* out       = (float*)d_out;
    float* out_y     = out;
    float* out_loss  = out + (size_t)ROWS_;
    float* out_alpha = out + (size_t)ROWS_ + 1;
    float* out_m     = out_alpha + (size_t)B_ * Y_ * L_;

    cudaFuncSetAttribute(gemm1_k, cudaFuncAttributeMaxDynamicSharedMemorySize, SMEM_GEMM);
    cudaFuncSetAttribute(gemm2_k, cudaFuncAttributeMaxDynamicSharedMemorySize, SMEM_GEMM);

    split_U_kernel<<<YPAD_ * D_ / 256, 256>>>(U);
    split_x_kernel<<<dim3(D_ / 32, L_ / 32, B_), dim3(32, 8)>>>(x);

    gemm1_k<<<dim3(L_ / 128, YPAD_ / 128, B_), 256, SMEM_GEMM>>>(out_alpha);

    softmax_split<<<ROWS_, 256>>>(out_alpha);

    gemm2_k<<<dim3(D_ / 128, YPAD_ / 128, B_), 256, SMEM_GEMM>>>(out_m);

    head_kernel<<<Y_, 256>>>(out_m, FW, bias, target, out_y);
    loss_reduce<<<1, 1024>>>(out_loss);
}

// round 13
// speedup vs baseline: 3.3360x; 1.0832x over previous
#include <cuda_runtime.h>
#include <cuda_bf16.h>
#include <math.h>
#include <stdint.h>

#define B_    8
#define L_    2048
#define D_    512
#define Y_    8921
#define YPAD_ 8960                 // 70 * 128
#define ROWS_ (B_ * Y_)            // 71368

// ---- static device scratch (no runtime allocation allowed) ----
__device__ float g_partials[Y_];
__device__ __align__(16) __nv_bfloat16 g_U_hi[YPAD_ * D_];
__device__ __align__(16) __nv_bfloat16 g_U_lo[YPAD_ * D_];
__device__ __align__(16) __nv_bfloat16 g_x_hi[B_ * L_ * D_];                  // [b][l][d]
__device__ __align__(16) __nv_bfloat16 g_x_lo[B_ * L_ * D_];
__device__ __align__(16) __nv_bfloat16 g_xT_hi[B_ * D_ * L_];                 // [b][d][l]
__device__ __align__(16) __nv_bfloat16 g_xT_lo[B_ * D_ * L_];
__device__ __align__(16) __nv_bfloat16 g_alpha_hi[(size_t)B_ * YPAD_ * L_];
__device__ __align__(16) __nv_bfloat16 g_alpha_lo[(size_t)B_ * YPAD_ * L_];

// ---- helpers ----
__device__ __forceinline__ uint32_t smem_u32(const void* p) {
    uint32_t a;
    asm("{ .reg .u64 t; cvta.to.shared.u64 t, %1; cvt.u32.u64 %0, t; }" : "=r"(a) : "l"(p));
    return a;
}
__device__ __forceinline__ void ldsm4(uint32_t addr, uint32_t* r) {
    asm volatile("ldmatrix.sync.aligned.m8n8.x4.shared.b16 {%0,%1,%2,%3}, [%4];"
        : "=r"(r[0]), "=r"(r[1]), "=r"(r[2]), "=r"(r[3]) : "r"(addr));
}
__device__ __forceinline__ void mma16816(float* c, const uint32_t* a, const uint32_t* b) {
    asm volatile("mma.sync.aligned.m16n8k16.row.col.f32.bf16.bf16.f32 "
        "{%0,%1,%2,%3}, {%4,%5,%6,%7}, {%8,%9}, {%0,%1,%2,%3};"
        : "+f"(c[0]), "+f"(c[1]), "+f"(c[2]), "+f"(c[3])
        : "r"(a[0]), "r"(a[1]), "r"(a[2]), "r"(a[3]), "r"(b[0]), "r"(b[1]));
}

// SMEM tile geometry: 128 rows x 32 bf16 (64B data) with 80B pitch.
// 80 = 5*16: every row 16B-aligned (ldmatrix-legal); 8-row phases hit banks
// (20r mod 32) = full partition -> conflict-free ldmatrix by construction.
#define PITCH_B   80
#define TILE_SB   (128 * PITCH_B)     // 10240
#define STAGE_SB  (4 * TILE_SB)       // 40960 (A_hi, A_lo, B_hi, B_lo)
#define SMEM_GEMM (2 * STAGE_SB)      // 81920, double-buffered

// cp.async one 128(rows) x 32(k bf16 = 64B) tile into padded-pitch SMEM.
__device__ __forceinline__ void cp_tile32(uint32_t dst, const __nv_bfloat16* __restrict__ src,
                                          int kb, int ldk, int tid)
{
#pragma unroll
    for (int i = 0; i < 2; i++) {
        int seg = tid + i * 256;            // 0..511 segments of 16B
        int row = seg >> 2;                 // 4 segments per row
        int u   = seg & 3;
        const void* g = src + (size_t)row * ldk + kb + u * 8;
        uint32_t d = dst + (uint32_t)row * PITCH_B + (uint32_t)(u << 4);
        asm volatile("cp.async.ca.shared.global [%0], [%1], 16;" :: "r"(d), "l"(g));
    }
}

// ---------------------------------------------------------------------------
// HMMA GEMM body: C[m][n] = sum_k A[m][k] * B[n][k] for this CTA's 128x128 tile.
// A,B pre-split bf16 hi/lo, K-contiguous. fp32 accumulate, 3-product split.
// 8 warps (4m x 2n), K-chunk 32, cp.async 2-stage pipeline, ldmatrix fragments.
// ---------------------------------------------------------------------------
__device__ __forceinline__ void gemm_body(
    const __nv_bfloat16* pAh, const __nv_bfloat16* pAl,
    const __nv_bfloat16* pBh, const __nv_bfloat16* pBl,
    int ldkA, int ldkB, int K,
    float* outp, int ldo, int y0, int n0)
{
    extern __shared__ __align__(16) uint8_t smem[];
    uint32_t sb = smem_u32(smem);

    const int tid  = threadIdx.x;
    const int lane = tid & 31;
    const int wid  = tid >> 5;
    const int grp  = lane >> 2;            // groupID (0..7)
    const int tig  = lane & 3;             // threadID_in_group (0..3)
    const int wm = wid & 3;                // 4 m-groups of 32 rows
    const int wn = wid >> 2;               // 2 n-groups of 64 cols

    // ldmatrix lane-address components (verified against PTX fragment tables):
    // A x4: matrices {rows0-7 k0, rows8-15 k0, rows0-7 k8, rows8-15 k8}
    const int a_row = lane & 15;           // row within 16-row fragment
    const int a_k8  = lane >> 4;           // k8-half selector
    // B x4: matrices {n0-7 k0, n0-7 k8, n8-15 k0, n8-15 k8} (two n8 blocks)
    const int b_row = (lane & 7) + ((lane >> 4) << 3);   // n within 16-block
    const int b_k8  = (lane >> 3) & 1;

    float acc[2][8][4];
#pragma unroll
    for (int t = 0; t < 2; t++)
#pragma unroll
        for (int q = 0; q < 8; q++)
#pragma unroll
            for (int e = 0; e < 4; e++) acc[t][q][e] = 0.f;

    const int NC = K >> 5;                 // K-chunk 32

    // prologue: chunk 0 -> stage 0
    {
        uint32_t st = sb;
        cp_tile32(st,               pAh, 0, ldkA, tid);
        cp_tile32(st + TILE_SB,     pAl, 0, ldkA, tid);
        cp_tile32(st + 2 * TILE_SB, pBh, 0, ldkB, tid);
        cp_tile32(st + 3 * TILE_SB, pBl, 0, ldkB, tid);
        asm volatile("cp.async.commit_group;");
    }

    for (int c = 0; c < NC; c++) {
        if (c + 1 < NC) {
            uint32_t st = sb + (uint32_t)((c + 1) & 1) * STAGE_SB;
            int kb = (c + 1) * 32;
            cp_tile32(st,               pAh, kb, ldkA, tid);
            cp_tile32(st + TILE_SB,     pAl, kb, ldkA, tid);
            cp_tile32(st + 2 * TILE_SB, pBh, kb, ldkB, tid);
            cp_tile32(st + 3 * TILE_SB, pBl, kb, ldkB, tid);
            asm volatile("cp.async.commit_group;");
            asm volatile("cp.async.wait_group 1;");   // chunk c complete
        } else {
            asm volatile("cp.async.wait_group 0;");
        }
        __syncthreads();                               // chunk c visible to all

        uint32_t st  = sb + (uint32_t)(c & 1) * STAGE_SB;
        const uint32_t sAh = st;
        const uint32_t sAl = st + TILE_SB;
        const uint32_t sBh = st + 2 * TILE_SB;
        const uint32_t sBl = st + 3 * TILE_SB;

#pragma unroll
        for (int s = 0; s < 2; s++) {       // two k16 steps in the 32-chunk
            const uint32_t koffA = (uint32_t)((s * 16 + a_k8 * 8) * 2);
            const uint32_t koffB = (uint32_t)((s * 16 + b_k8 * 8) * 2);

            // --- A fragments via ldmatrix.x4: one per (t, hi/lo) ---
            uint32_t ahf[2][4], alf[2][4];
#pragma unroll
            for (int t = 0; t < 2; t++) {
                uint32_t oa = (uint32_t)(wm * 32 + t * 16 + a_row) * PITCH_B + koffA;
                ldsm4(sAh + oa, ahf[t]);
                ldsm4(sAl + oa, alf[t]);
            }
            // --- B fragments via ldmatrix.x4: each covers two n8 blocks ---
            uint32_t bhf[4][4], blf[4][4];
#pragma unroll
            for (int jj = 0; jj < 4; jj++) {
                uint32_t ob = (uint32_t)(wn * 64 + jj * 16 + b_row) * PITCH_B + koffB;
                ldsm4(sBh + ob, bhf[jj]);
                ldsm4(sBl + ob, blf[jj]);
            }
            // --- 3 split MMAs per (t, n8 block) ---
#pragma unroll
            for (int jj = 0; jj < 4; jj++) {
#pragma unroll
                for (int t = 0; t < 2; t++) {
                    mma16816(acc[t][2 * jj],     ahf[t], &bhf[jj][0]);
                    mma16816(acc[t][2 * jj],     ahf[t], &blf[jj][0]);
                    mma16816(acc[t][2 * jj],     alf[t], &bhf[jj][0]);
                    mma16816(acc[t][2 * jj + 1], ahf[t], &bhf[jj][2]);
                    mma16816(acc[t][2 * jj + 1], ahf[t], &blf[jj][2]);
                    mma16816(acc[t][2 * jj + 1], alf[t], &bhf[jj][2]);
                }
            }
        }
        __syncthreads();    // all warps done reading stage (c&1) before reuse
    }

    // Epilogue: direct stores. Quad (tig 0..3) covers 8 consecutive cols of one
    // row -> each 32B sector fully written. Guard m-rows >= Y_ (padding).
#pragma unroll
    for (int t = 0; t < 2; t++) {
        int r  = y0 + wm * 32 + t * 16 + grp;
#pragma unroll
        for (int q = 0; q < 8; q++) {
            int cc = n0 + wn * 64 + q * 8 + tig * 2;
            if (r < Y_) {
                outp[(size_t)r * ldo + cc]     = acc[t][q][0];
                outp[(size_t)r * ldo + cc + 1] = acc[t][q][1];
            }
            if (r + 8 < Y_) {
                outp[(size_t)(r + 8) * ldo + cc]     = acc[t][q][2];
                outp[(size_t)(r + 8) * ldo + cc + 1] = acc[t][q][3];
            }
        }
    }
}

// GEMM1 wrapper: scores[b,y,l] = U[y,:] . x[b,l,:]
// Device-global operands bound HERE (device code), not passed from host.
__global__ void __launch_bounds__(256) gemm1_k(float* __restrict__ Sout)
{
    const int b  = blockIdx.z;
    const int y0 = blockIdx.y * 128;
    const int l0 = blockIdx.x * 128;
    gemm_body(g_U_hi + (size_t)y0 * D_,
              g_U_lo + (size_t)y0 * D_,
              g_x_hi + ((size_t)b * L_ + l0) * D_,
              g_x_lo + ((size_t)b * L_ + l0) * D_,
              D_, D_, D_,
              Sout + (size_t)b * Y_ * L_, L_, y0, l0);
}

// GEMM2 wrapper: m[b,y,d] = alpha[b,y,:] . xT[b,d,:]
__global__ void __launch_bounds__(256) gemm2_k(float* __restrict__ Mout)
{
    const int b  = blockIdx.z;
    const int y0 = blockIdx.y * 128;
    const int n0 = blockIdx.x * 128;
    gemm_body(g_alpha_hi + ((size_t)b * YPAD_ + y0) * L_,
              g_alpha_lo + ((size_t)b * YPAD_ + y0) * L_,
              g_xT_hi + ((size_t)b * D_ + n0) * L_,
              g_xT_lo + ((size_t)b * D_ + n0) * L_,
              L_, L_, L_,
              Mout + (size_t)b * Y_ * D_, D_, y0, n0);
}

// ---------------------------------------------------------------------------
// Prep: split U (zero-padded to YPAD rows) and x (plus transposed xT).
// ---------------------------------------------------------------------------
__global__ __launch_bounds__(256) void split_U_kernel(const float* __restrict__ U)
{
    int idx = blockIdx.x * 256 + threadIdx.x;     // over YPAD_*D_
    int y = idx >> 9;
    float v = (y < Y_) ? U[idx] : 0.f;
    __nv_bfloat16 h = __float2bfloat16(v);
    g_U_hi[idx] = h;
    g_U_lo[idx] = __float2bfloat16(v - __bfloat162float(h));
}

__global__ __launch_bounds__(256) void split_x_kernel(const float* __restrict__ X)
{
    __shared__ float tile[32][33];
    int b = blockIdx.z, d0 = blockIdx.x * 32, l0 = blockIdx.y * 32;
    int tx = threadIdx.x, ty = threadIdx.y;       // (32, 8)
#pragma unroll
    for (int i = 0; i < 4; i++) {
        int l = l0 + ty + i * 8;
        size_t o = ((size_t)b * L_ + l) * D_ + d0 + tx;
        float v = X[o];
        tile[ty + i * 8][tx] = v;
        __nv_bfloat16 h = __float2bfloat16(v);
        g_x_hi[o] = h;
        g_x_lo[o] = __float2bfloat16(v - __bfloat162float(h));
    }
    __syncthreads();
#pragma unroll
    for (int i = 0; i < 4; i++) {
        int d = d0 + ty + i * 8;
        float v = tile[tx][ty + i * 8];
        size_t o = ((size_t)b * D_ + d) * L_ + l0 + tx;
        __nv_bfloat16 h = __float2bfloat16(v);
        g_xT_hi[o] = h;
        g_xT_lo[o] = __float2bfloat16(v - __bfloat162float(h));
    }
}

// ---------------------------------------------------------------------------
// Softmax over L=2048 rows, in place; also emits bf16 hi/lo split of alpha.
// ---------------------------------------------------------------------------
__global__ __launch_bounds__(256) void softmax_split(float* __restrict__ S)
{
    const int r = blockIdx.x;                     // 0..ROWS_-1
    const int b = r / Y_, y = r - b * Y_;
    float* p = S + (size_t)r * L_;
    __nv_bfloat16* ph = g_alpha_hi + ((size_t)b * YPAD_ + y) * L_;
    __nv_bfloat16* pl = g_alpha_lo + ((size_t)b * YPAD_ + y) * L_;
    const int t = threadIdx.x;

    float v[8];
    float mx = -3.402823466e38f;
#pragma unroll
    for (int j = 0; j < 8; j++) {
        v[j] = p[t + j * 256];
        mx = fmaxf(mx, v[j]);
    }
    __shared__ float sm[8];
#pragma unroll
    for (int o = 16; o; o >>= 1) mx = fmaxf(mx, __shfl_xor_sync(0xffffffffu, mx, o));
    if ((t & 31) == 0) sm[t >> 5] = mx;
    __syncthreads();
    mx = sm[0];
#pragma unroll
    for (int i = 1; i < 8; i++) mx = fmaxf(mx, sm[i]);
    __syncthreads();

    float sum = 0.f;
#pragma unroll
    for (int j = 0; j < 8; j++) { v[j] = expf(v[j] - mx); sum += v[j]; }
#pragma unroll
    for (int o = 16; o; o >>= 1) sum += __shfl_xor_sync(0xffffffffu, sum, o);
    if ((t & 31) == 0) sm[t >> 5] = sum;
    __syncthreads();
    sum = 0.f;
#pragma unroll
    for (int i = 0; i < 8; i++) sum += sm[i];
    float inv = 1.f / sum;

#pragma unroll
    for (int j = 0; j < 8; j++) {
        float o = v[j] * inv;
        int ix = t + j * 256;
        p[ix] = o;
        __nv_bfloat16 h = __float2bfloat16(o);
        ph[ix] = h;
        pl[ix] = __float2bfloat16(o - __bfloat162float(h));
    }
}

// ---------------------------------------------------------------------------
// Head + loss (unchanged).
// ---------------------------------------------------------------------------
__global__ __launch_bounds__(256) void head_kernel(
    const float* __restrict__ Mo, const float* __restrict__ FW,
    const float* __restrict__ bias, const float* __restrict__ target,
    float* __restrict__ Yout)
{
    const int w = threadIdx.x >> 5, lane = threadIdx.x & 31;
    const int g = blockIdx.x * 8 + w;
    const int yy = g % Y_;
    const float* mr = Mo + (size_t)g * D_;
    const float* fr = FW + (size_t)yy * D_;

    float s = 0.f;
#pragma unroll
    for (int j = 0; j < 16; j++)
        s = fmaf(mr[lane + j * 32], fr[lane + j * 32], s);
#pragma unroll
    for (int o = 16; o; o >>= 1) s += __shfl_xor_sync(0xffffffffu, s, o);

    __shared__ float sm[8];
    if (lane == 0) {
        float yv = s + bias[yy];
        Yout[g] = yv;
        float t = target[g];
        sm[w] = fmaxf(yv, 0.f) - yv * t + log1pf(expf(-fabsf(yv)));
    }
    __syncthreads();
    if (threadIdx.x == 0) {
        float acc = 0.f;
#pragma unroll
        for (int i = 0; i < 8; i++) acc += sm[i];
        g_partials[blockIdx.x] = acc;
    }
}

__global__ __launch_bounds__(1024) void loss_reduce(float* __restrict__ out)
{
    __shared__ double sm[32];
    double s = 0.0;
    for (int i = threadIdx.x; i < Y_; i += 1024) s += (double)g_partials[i];
#pragma unroll
    for (int o = 16; o; o >>= 1) s += __shfl_xor_sync(0xffffffffu, s, o);
    if ((threadIdx.x & 31) == 0) sm[threadIdx.x >> 5] = s;
    __syncthreads();
    if (threadIdx.x == 0) {
        double acc = 0.0;
#pragma unroll
        for (int i = 0; i < 32; i++) acc += sm[i];
        out[0] = (float)(acc / (double)ROWS_);
    }
}

// ---------------------------------------------------------------------------
// Launch. Inputs: x, target, text_inputs(unused), U_weight, final_weight,
// final_bias. Output tuple: (y, loss, alpha, m) flattened into d_out.
// Only harness-provided device pointers cross the host/device boundary.
// ---------------------------------------------------------------------------
extern "C" void kernel_launch(void* const* d_in, const int* in_sizes, int n_in,
                              void* d_out, int out_size)
{
    const float* x      = (const float*)d_in[0];
    const float* target = (const float*)d_in[1];
    const float* U      = (const float*)d_in[3];
    const float* FW     = (const float*)d_in[4];
    const float* bias   = (const float*)d_in[5];

    float* out       = (float*)d_out;
    float* out_y     = out;
    float* out_loss  = out + (size_t)ROWS_;
    float* out_alpha = out + (size_t)ROWS_ + 1;
    float* out_m     = out_alpha + (size_t)B_ * Y_ * L_;

    cudaFuncSetAttribute(gemm1_k, cudaFuncAttributeMaxDynamicSharedMemorySize, SMEM_GEMM);
    cudaFuncSetAttribute(gemm2_k, cudaFuncAttributeMaxDynamicSharedMemorySize, SMEM_GEMM);

    split_U_kernel<<<YPAD_ * D_ / 256, 256>>>(U);
    split_x_kernel<<<dim3(D_ / 32, L_ / 32, B_), dim3(32, 8)>>>(x);

    gemm1_k<<<dim3(L_ / 128, YPAD_ / 128, B_), 256, SMEM_GEMM>>>(out_alpha);

    softmax_split<<<ROWS_, 256>>>(out_alpha);

    gemm2_k<<<dim3(D_ / 128, YPAD_ / 128, B_), 256, SMEM_GEMM>>>(out_m);

    head_kernel<<<Y_, 256>>>(out_m, FW, bias, target, out_y);
    loss_reduce<<<1, 1024>>>(out_loss);
}

// round 14
// speedup vs baseline: 3.3932x; 1.0172x over previous
#include <cuda_runtime.h>
#include <cuda_bf16.h>
#include <math.h>
#include <stdint.h>

#define B_    8
#define L_    2048
#define D_    512
#define Y_    8921
#define YPAD_ 8960                 // 70 * 128
#define ROWS_ (B_ * Y_)            // 71368

// ---- static device scratch (no runtime allocation allowed) ----
__device__ float g_partials[Y_];
__device__ __align__(16) __nv_bfloat16 g_U_hi[YPAD_ * D_];
__device__ __align__(16) __nv_bfloat16 g_U_lo[YPAD_ * D_];
__device__ __align__(16) __nv_bfloat16 g_x_hi[B_ * L_ * D_];                  // [b][l][d]
__device__ __align__(16) __nv_bfloat16 g_x_lo[B_ * L_ * D_];
__device__ __align__(16) __nv_bfloat16 g_xT_hi[B_ * D_ * L_];                 // [b][d][l]
__device__ __align__(16) __nv_bfloat16 g_xT_lo[B_ * D_ * L_];
__device__ __align__(16) __nv_bfloat16 g_alpha_hi[(size_t)B_ * YPAD_ * L_];
__device__ __align__(16) __nv_bfloat16 g_alpha_lo[(size_t)B_ * YPAD_ * L_];

// ---- helpers ----
__device__ __forceinline__ uint32_t smem_u32(const void* p) {
    uint32_t a;
    asm("{ .reg .u64 t; cvta.to.shared.u64 t, %1; cvt.u32.u64 %0, t; }" : "=r"(a) : "l"(p));
    return a;
}
__device__ __forceinline__ void ldsm4(uint32_t addr, uint32_t* r) {
    asm volatile("ldmatrix.sync.aligned.m8n8.x4.shared.b16 {%0,%1,%2,%3}, [%4];"
        : "=r"(r[0]), "=r"(r[1]), "=r"(r[2]), "=r"(r[3]) : "r"(addr));
}
__device__ __forceinline__ void mma16816(float* c, const uint32_t* a, const uint32_t* b) {
    asm volatile("mma.sync.aligned.m16n8k16.row.col.f32.bf16.bf16.f32 "
        "{%0,%1,%2,%3}, {%4,%5,%6,%7}, {%8,%9}, {%0,%1,%2,%3};"
        : "+f"(c[0]), "+f"(c[1]), "+f"(c[2]), "+f"(c[3])
        : "r"(a[0]), "r"(a[1]), "r"(a[2]), "r"(a[3]), "r"(b[0]), "r"(b[1]));
}

// SMEM tile geometry: 128 rows x 32 bf16 (64B data) with 80B pitch.
// 80 = 5*16: every row 16B-aligned (ldmatrix-legal); 8-row phases hit banks
// (20r mod 32) = full partition -> conflict-free ldmatrix by construction.
#define PITCH_B   80
#define TILE_SB   (128 * PITCH_B)     // 10240
#define STAGE_SB  (4 * TILE_SB)       // 40960 (A_hi, A_lo, B_hi, B_lo)
#define SMEM_GEMM (2 * STAGE_SB)      // 81920, double-buffered (2 CTAs/SM fit)

// cp.async one 128(rows) x 32(k bf16 = 64B) tile into padded-pitch SMEM.
__device__ __forceinline__ void cp_tile32(uint32_t dst, const __nv_bfloat16* __restrict__ src,
                                          int kb, int ldk, int tid)
{
#pragma unroll
    for (int i = 0; i < 2; i++) {
        int seg = tid + i * 256;            // 0..511 segments of 16B
        int row = seg >> 2;                 // 4 segments per row
        int u   = seg & 3;
        const void* g = src + (size_t)row * ldk + kb + u * 8;
        uint32_t d = dst + (uint32_t)row * PITCH_B + (uint32_t)(u << 4);
        asm volatile("cp.async.ca.shared.global [%0], [%1], 16;" :: "r"(d), "l"(g));
    }
}

// ---------------------------------------------------------------------------
// HMMA GEMM body: C[m][n] = sum_k A[m][k] * B[n][k] for this CTA's 128x128 tile.
// A,B pre-split bf16 hi/lo, K-contiguous. fp32 accumulate, 3-product split.
// 8 warps (4m x 2n), K-chunk 32, cp.async 2-stage pipeline, ldmatrix fragments.
// B fragments loaded per n16-block inside the MMA loop to cap live registers
// (~100) so 2 CTAs/SM are resident (see __launch_bounds__ on the wrappers).
// ---------------------------------------------------------------------------
__device__ __forceinline__ void gemm_body(
    const __nv_bfloat16* pAh, const __nv_bfloat16* pAl,
    const __nv_bfloat16* pBh, const __nv_bfloat16* pBl,
    int ldkA, int ldkB, int K,
    float* outp, int ldo, int y0, int n0)
{
    extern __shared__ __align__(16) uint8_t smem[];
    uint32_t sb = smem_u32(smem);

    const int tid  = threadIdx.x;
    const int lane = tid & 31;
    const int wid  = tid >> 5;
    const int grp  = lane >> 2;            // groupID (0..7)
    const int tig  = lane & 3;             // threadID_in_group (0..3)
    const int wm = wid & 3;                // 4 m-groups of 32 rows
    const int wn = wid >> 2;               // 2 n-groups of 64 cols

    // ldmatrix lane-address components (verified against PTX fragment tables):
    const int a_row = lane & 15;           // A: row within 16-row fragment
    const int a_k8  = lane >> 4;           // A: k8-half selector
    const int b_row = (lane & 7) + ((lane >> 4) << 3);   // B: n within 16-block
    const int b_k8  = (lane >> 3) & 1;     // B: k8-half selector

    float acc[2][8][4];
#pragma unroll
    for (int t = 0; t < 2; t++)
#pragma unroll
        for (int q = 0; q < 8; q++)
#pragma unroll
            for (int e = 0; e < 4; e++) acc[t][q][e] = 0.f;

    const int NC = K >> 5;                 // K-chunk 32

    // prologue: chunk 0 -> stage 0
    {
        uint32_t st = sb;
        cp_tile32(st,               pAh, 0, ldkA, tid);
        cp_tile32(st + TILE_SB,     pAl, 0, ldkA, tid);
        cp_tile32(st + 2 * TILE_SB, pBh, 0, ldkB, tid);
        cp_tile32(st + 3 * TILE_SB, pBl, 0, ldkB, tid);
        asm volatile("cp.async.commit_group;");
    }

    for (int c = 0; c < NC; c++) {
        if (c + 1 < NC) {
            uint32_t st = sb + (uint32_t)((c + 1) & 1) * STAGE_SB;
            int kb = (c + 1) * 32;
            cp_tile32(st,               pAh, kb, ldkA, tid);
            cp_tile32(st + TILE_SB,     pAl, kb, ldkA, tid);
            cp_tile32(st + 2 * TILE_SB, pBh, kb, ldkB, tid);
            cp_tile32(st + 3 * TILE_SB, pBl, kb, ldkB, tid);
            asm volatile("cp.async.commit_group;");
            asm volatile("cp.async.wait_group 1;");   // chunk c complete
        } else {
            asm volatile("cp.async.wait_group 0;");
        }
        __syncthreads();                               // chunk c visible to all

        uint32_t st  = sb + (uint32_t)(c & 1) * STAGE_SB;
        const uint32_t sAh = st;
        const uint32_t sAl = st + TILE_SB;
        const uint32_t sBh = st + 2 * TILE_SB;
        const uint32_t sBl = st + 3 * TILE_SB;

#pragma unroll
        for (int s = 0; s < 2; s++) {       // two k16 steps in the 32-chunk
            const uint32_t koffA = (uint32_t)((s * 16 + a_k8 * 8) * 2);
            const uint32_t koffB = (uint32_t)((s * 16 + b_k8 * 8) * 2);

            // --- A fragments via ldmatrix.x4: one per (t, hi/lo) ---
            uint32_t ahf[2][4], alf[2][4];
#pragma unroll
            for (int t = 0; t < 2; t++) {
                uint32_t oa = (uint32_t)(wm * 32 + t * 16 + a_row) * PITCH_B + koffA;
                ldsm4(sAh + oa, ahf[t]);
                ldsm4(sAl + oa, alf[t]);
            }
            // --- B fragments per n16 block, loaded just-in-time (low reg use) ---
#pragma unroll
            for (int jj = 0; jj < 4; jj++) {
                uint32_t ob = (uint32_t)(wn * 64 + jj * 16 + b_row) * PITCH_B + koffB;
                uint32_t bhf[4], blf[4];
                ldsm4(sBh + ob, bhf);
                ldsm4(sBl + ob, blf);
#pragma unroll
                for (int t = 0; t < 2; t++) {
                    mma16816(acc[t][2 * jj],     ahf[t], &bhf[0]);
                    mma16816(acc[t][2 * jj],     ahf[t], &blf[0]);
                    mma16816(acc[t][2 * jj],     alf[t], &bhf[0]);
                    mma16816(acc[t][2 * jj + 1], ahf[t], &bhf[2]);
                    mma16816(acc[t][2 * jj + 1], ahf[t], &blf[2]);
                    mma16816(acc[t][2 * jj + 1], alf[t], &bhf[2]);
                }
            }
        }
        __syncthreads();    // all warps done reading stage (c&1) before reuse
    }

    // Epilogue: direct stores. Quad (tig 0..3) covers 8 consecutive cols of one
    // row -> each 32B sector fully written. Guard m-rows >= Y_ (padding).
#pragma unroll
    for (int t = 0; t < 2; t++) {
        int r  = y0 + wm * 32 + t * 16 + grp;
#pragma unroll
        for (int q = 0; q < 8; q++) {
            int cc = n0 + wn * 64 + q * 8 + tig * 2;
            if (r < Y_) {
                outp[(size_t)r * ldo + cc]     = acc[t][q][0];
                outp[(size_t)r * ldo + cc + 1] = acc[t][q][1];
            }
            if (r + 8 < Y_) {
                outp[(size_t)(r + 8) * ldo + cc]     = acc[t][q][2];
                outp[(size_t)(r + 8) * ldo + cc + 1] = acc[t][q][3];
            }
        }
    }
}

// GEMM1 wrapper: scores[b,y,l] = U[y,:] . x[b,l,:]
// minBlocksPerMultiprocessor=2 forces <=128 regs -> 2 CTAs/SM co-resident.
__global__ void __launch_bounds__(256, 2) gemm1_k(float* __restrict__ Sout)
{
    const int b  = blockIdx.z;
    const int y0 = blockIdx.y * 128;
    const int l0 = blockIdx.x * 128;
    gemm_body(g_U_hi + (size_t)y0 * D_,
              g_U_lo + (size_t)y0 * D_,
              g_x_hi + ((size_t)b * L_ + l0) * D_,
              g_x_lo + ((size_t)b * L_ + l0) * D_,
              D_, D_, D_,
              Sout + (size_t)b * Y_ * L_, L_, y0, l0);
}

// GEMM2 wrapper: m[b,y,d] = alpha[b,y,:] . xT[b,d,:]
__global__ void __launch_bounds__(256, 2) gemm2_k(float* __restrict__ Mout)
{
    const int b  = blockIdx.z;
    const int y0 = blockIdx.y * 128;
    const int n0 = blockIdx.x * 128;
    gemm_body(g_alpha_hi + ((size_t)b * YPAD_ + y0) * L_,
              g_alpha_lo + ((size_t)b * YPAD_ + y0) * L_,
              g_xT_hi + ((size_t)b * D_ + n0) * L_,
              g_xT_lo + ((size_t)b * D_ + n0) * L_,
              L_, L_, L_,
              Mout + (size_t)b * Y_ * D_, D_, y0, n0);
}

// ---------------------------------------------------------------------------
// Prep: split U (zero-padded to YPAD rows) and x (plus transposed xT).
// ---------------------------------------------------------------------------
__global__ __launch_bounds__(256) void split_U_kernel(const float* __restrict__ U)
{
    int idx = blockIdx.x * 256 + threadIdx.x;     // over YPAD_*D_
    int y = idx >> 9;
    float v = (y < Y_) ? U[idx] : 0.f;
    __nv_bfloat16 h = __float2bfloat16(v);
    g_U_hi[idx] = h;
    g_U_lo[idx] = __float2bfloat16(v - __bfloat162float(h));
}

__global__ __launch_bounds__(256) void split_x_kernel(const float* __restrict__ X)
{
    __shared__ float tile[32][33];
    int b = blockIdx.z, d0 = blockIdx.x * 32, l0 = blockIdx.y * 32;
    int tx = threadIdx.x, ty = threadIdx.y;       // (32, 8)
#pragma unroll
    for (int i = 0; i < 4; i++) {
        int l = l0 + ty + i * 8;
        size_t o = ((size_t)b * L_ + l) * D_ + d0 + tx;
        float v = X[o];
        tile[ty + i * 8][tx] = v;
        __nv_bfloat16 h = __float2bfloat16(v);
        g_x_hi[o] = h;
        g_x_lo[o] = __float2bfloat16(v - __bfloat162float(h));
    }
    __syncthreads();
#pragma unroll
    for (int i = 0; i < 4; i++) {
        int d = d0 + ty + i * 8;
        float v = tile[tx][ty + i * 8];
        size_t o = ((size_t)b * D_ + d) * L_ + l0 + tx;
        __nv_bfloat16 h = __float2bfloat16(v);
        g_xT_hi[o] = h;
        g_xT_lo[o] = __float2bfloat16(v - __bfloat162float(h));
    }
}

// ---------------------------------------------------------------------------
// Softmax over L=2048 rows, in place; also emits bf16 hi/lo split of alpha.
// ---------------------------------------------------------------------------
__global__ __launch_bounds__(256) void softmax_split(float* __restrict__ S)
{
    const int r = blockIdx.x;                     // 0..ROWS_-1
    const int b = r / Y_, y = r - b * Y_;
    float* p = S + (size_t)r * L_;
    __nv_bfloat16* ph = g_alpha_hi + ((size_t)b * YPAD_ + y) * L_;
    __nv_bfloat16* pl = g_alpha_lo + ((size_t)b * YPAD_ + y) * L_;
    const int t = threadIdx.x;

    float v[8];
    float mx = -3.402823466e38f;
#pragma unroll
    for (int j = 0; j < 8; j++) {
        v[j] = p[t + j * 256];
        mx = fmaxf(mx, v[j]);
    }
    __shared__ float sm[8];
#pragma unroll
    for (int o = 16; o; o >>= 1) mx = fmaxf(mx, __shfl_xor_sync(0xffffffffu, mx, o));
    if ((t & 31) == 0) sm[t >> 5] = mx;
    __syncthreads();
    mx = sm[0];
#pragma unroll
    for (int i = 1; i < 8; i++) mx = fmaxf(mx, sm[i]);
    __syncthreads();

    float sum = 0.f;
#pragma unroll
    for (int j = 0; j < 8; j++) { v[j] = expf(v[j] - mx); sum += v[j]; }
#pragma unroll
    for (int o = 16; o; o >>= 1) sum += __shfl_xor_sync(0xffffffffu, sum, o);
    if ((t & 31) == 0) sm[t >> 5] = sum;
    __syncthreads();
    sum = 0.f;
#pragma unroll
    for (int i = 0; i < 8; i++) sum += sm[i];
    float inv = 1.f / sum;

#pragma unroll
    for (int j = 0; j < 8; j++) {
        float o = v[j] * inv;
        int ix = t + j * 256;
        p[ix] = o;
        __nv_bfloat16 h = __float2bfloat16(o);
        ph[ix] = h;
        pl[ix] = __float2bfloat16(o - __bfloat162float(h));
    }
}

// ---------------------------------------------------------------------------
// Head + loss (unchanged).
// ---------------------------------------------------------------------------
__global__ __launch_bounds__(256) void head_kernel(
    const float* __restrict__ Mo, const float* __restrict__ FW,
    const float* __restrict__ bias, const float* __restrict__ target,
    float* __restrict__ Yout)
{
    const int w = threadIdx.x >> 5, lane = threadIdx.x & 31;
    const int g = blockIdx.x * 8 + w;
    const int yy = g % Y_;
    const float* mr = Mo + (size_t)g * D_;
    const float* fr = FW + (size_t)yy * D_;

    float s = 0.f;
#pragma unroll
    for (int j = 0; j < 16; j++)
        s = fmaf(mr[lane + j * 32], fr[lane + j * 32], s);
#pragma unroll
    for (int o = 16; o; o >>= 1) s += __shfl_xor_sync(0xffffffffu, s, o);

    __shared__ float sm[8];
    if (lane == 0) {
        float yv = s + bias[yy];
        Yout[g] = yv;
        float t = target[g];
        sm[w] = fmaxf(yv, 0.f) - yv * t + log1pf(expf(-fabsf(yv)));
    }
    __syncthreads();
    if (threadIdx.x == 0) {
        float acc = 0.f;
#pragma unroll
        for (int i = 0; i < 8; i++) acc += sm[i];
        g_partials[blockIdx.x] = acc;
    }
}

__global__ __launch_bounds__(1024) void loss_reduce(float* __restrict__ out)
{
    __shared__ double sm[32];
    double s = 0.0;
    for (int i = threadIdx.x; i < Y_; i += 1024) s += (double)g_partials[i];
#pragma unroll
    for (int o = 16; o; o >>= 1) s += __shfl_xor_sync(0xffffffffu, s, o);
    if ((threadIdx.x & 31) == 0) sm[threadIdx.x >> 5] = s;
    __syncthreads();
    if (threadIdx.x == 0) {
        double acc = 0.0;
#pragma unroll
        for (int i = 0; i < 32; i++) acc += sm[i];
        out[0] = (float)(acc / (double)ROWS_);
    }
}

// ---------------------------------------------------------------------------
// Launch. Inputs: x, target, text_inputs(unused), U_weight, final_weight,
// final_bias. Output tuple: (y, loss, alpha, m) flattened into d_out.
// Only harness-provided device pointers cross the host/device boundary.
// ---------------------------------------------------------------------------
extern "C" void kernel_launch(void* const* d_in, const int* in_sizes, int n_in,
                              void* d_out, int out_size)
{
    const float* x      = (const float*)d_in[0];
    const float* target = (const float*)d_in[1];
    const float* U      = (const float*)d_in[3];
    const float* FW     = (const float*)d_in[4];
    const float* bias   = (const float*)d_in[5];

    float* out       = (float*)d_out;
    float* out_y     = out;
    float* out_loss  = out + (size_t)ROWS_;
    float* out_alpha = out + (size_t)ROWS_ + 1;
    float* out_m     = out_alpha + (size_t)B_ * Y_ * L_;

    cudaFuncSetAttribute(gemm1_k, cudaFuncAttributeMaxDynamicSharedMemorySize, SMEM_GEMM);
    cudaFuncSetAttribute(gemm2_k, cudaFuncAttributeMaxDynamicSharedMemorySize, SMEM_GEMM);

    split_U_kernel<<<YPAD_ * D_ / 256, 256>>>(U);
    split_x_kernel<<<dim3(D_ / 32, L_ / 32, B_), dim3(32, 8)>>>(x);

    gemm1_k<<<dim3(L_ / 128, YPAD_ / 128, B_), 256, SMEM_GEMM>>>(out_alpha);

    softmax_split<<<ROWS_, 256>>>(out_alpha);

    gemm2_k<<<dim3(D_ / 128, YPAD_ / 128, B_), 256, SMEM_GEMM>>>(out_m);

    head_kernel<<<Y_, 256>>>(out_m, FW, bias, target, out_y);
    loss_reduce<<<1, 1024>>>(out_loss);
}